// round 14
// baseline (speedup 1.0000x reference)
#include <cuda_runtime.h>
#include <cuda_bf16.h>
#include <cstdint>

#define DD 512
#define QQ 8
#define CC 1024
#define MTOT 65536
#define MD ((size_t)MTOT*DD)
#define COMMIT_W 0.02f
#define TAU 2.0f
#define CSLOTS 32
#define NTILES 512

// ---------------- device scratch (no cudaMalloc allowed) ----------------
__device__ __align__(128) float g_resid[MD];                       // fp32 residual
__device__ __align__(128) __nv_bfloat16 g_Abf[MD];                 // bf16 residual
__device__ __align__(128) __nv_bfloat16 g_Bbf[(size_t)QQ*CC*DD];   // bf16 codebooks
__device__ float g_hn[QQ*CC];                                      // exact 0.5*||e||^2
__device__ float g_partial[(size_t)QQ*MTOT];                       // per-row loss parts
__device__ float g_stageLoss[QQ];
__device__ int   g_candcnt[MTOT];
__device__ unsigned long long g_cand[(size_t)MTOT*CSLOTS];
__device__ int   g_qcnt[QQ];                                       // stage-7 queue count
__device__ int   g_queue[MTOT];                                    // stage-7 slow rows
__device__ int   g_done[QQ*NTILES];                                // fused-resolve flags

// ---------------- helpers ----------------
static __device__ __forceinline__ uint32_t smem_u32(const void* p) {
    uint32_t a;
    asm("{ .reg .u64 t; cvta.to.shared.u64 t, %1; cvt.u32.u64 %0, t; }" : "=r"(a) : "l"(p));
    return a;
}
static __device__ __forceinline__ unsigned fkey(float s) {
    unsigned u = __float_as_uint(s);
    return (u & 0x80000000u) ? ~u : (u | 0x80000000u);
}
static __device__ __forceinline__ float unfkey(unsigned u) {
    return (u & 0x80000000u) ? __uint_as_float(u & 0x7FFFFFFFu) : __uint_as_float(~u);
}
// key orders by score desc, then LOWEST code (matches jnp.argmin tie-break)
static __device__ __forceinline__ unsigned long long makeKey(float s, int c) {
    return ((unsigned long long)fkey(s) << 32) | (unsigned)(0xFFFFFFFFu - (unsigned)c);
}
static __device__ __forceinline__ int   keyCode(unsigned long long k) { return (int)(0xFFFFFFFFu - (unsigned)(k & 0xFFFFFFFFu)); }
static __device__ __forceinline__ float keyScore(unsigned long long k) { return unfkey((unsigned)(k >> 32)); }
static __device__ __forceinline__ unsigned long long warpMaxU64(unsigned long long v) {
    #pragma unroll
    for (int m = 16; m > 0; m >>= 1) {
        unsigned long long o = __shfl_xor_sync(0xffffffffu, v, m);
        if (o > v) v = o;
    }
    return v;
}

#define LDSM4(R, addr) asm volatile( \
    "ldmatrix.sync.aligned.m8n8.x4.shared.b16 {%0,%1,%2,%3}, [%4];" \
    : "=r"((R)[0]),"=r"((R)[1]),"=r"((R)[2]),"=r"((R)[3]) : "r"(addr))

#define MMA16816(D, A, b0, b1) asm volatile( \
    "mma.sync.aligned.m16n8k16.row.col.f32.bf16.bf16.f32 " \
    "{%0,%1,%2,%3},{%4,%5,%6,%7},{%8,%9},{%0,%1,%2,%3};" \
    : "+f"((D)[0]),"+f"((D)[1]),"+f"((D)[2]),"+f"((D)[3]) \
    : "r"((A)[0]),"r"((A)[1]),"r"((A)[2]),"r"((A)[3]),"r"(b0),"r"(b1))

static __device__ __forceinline__ void cp16(uint32_t saddr, const void* gptr) {
    asm volatile("cp.async.cg.shared.global [%0], [%1], 16;"
                 :: "r"(saddr), "l"(__cvta_generic_to_global(gptr)));
}
static __device__ __forceinline__ void pack_bf16_8(const float* v, uint4& u) {
    unsigned h[8];
    #pragma unroll
    for (int i = 0; i < 8; ++i) {
        __nv_bfloat16 b = __float2bfloat16_rn(v[i]);
        h[i] = *(unsigned short*)&b;
    }
    u.x = h[0]|(h[1]<<16); u.y = h[2]|(h[3]<<16); u.z = h[4]|(h[5]<<16); u.w = h[6]|(h[7]<<16);
}
// R1-bit-exact score: sequential fp32 FMA over k ascending (float4 loads, scalar
// FMA order identical to the verified scalar version), minus exact hn.
static __device__ __forceinline__ float exact_score(const float* __restrict__ rr,
                                                    const float* __restrict__ e,
                                                    float hnv) {
    const float4* e4 = (const float4*)e;
    const float4* r4 = (const float4*)rr;
    float dot = 0.f;
    #pragma unroll 8
    for (int k = 0; k < DD / 4; ++k) {
        float4 ev = __ldg(&e4[k]);
        float4 rv = __ldg(&r4[k]);
        dot = __fmaf_rn(rv.x, ev.x, dot);
        dot = __fmaf_rn(rv.y, ev.y, dot);
        dot = __fmaf_rn(rv.z, ev.z, dot);
        dot = __fmaf_rn(rv.w, ev.w, dot);
    }
    return dot - hnv;
}

// shared update body: computes v = r - e, writes resid/Abf or final out, returns lsum
static __device__ __forceinline__ float do_update(int row, int id, int lane,
                                                  const float* __restrict__ cb,
                                                  float4 r0, float4 r1, float4 r2, float4 r3,
                                                  int writeA,
                                                  const float* __restrict__ x,
                                                  float* __restrict__ outQ) {
    float4* rp = (float4*)(g_resid + (size_t)row * DD);
    const int f4 = lane * 2;
    const float4* ep = (const float4*)(cb + (size_t)id * DD);
    float4 e0 = __ldg(ep + f4), e1 = __ldg(ep + f4 + 1);
    float4 e2 = __ldg(ep + f4 + 64), e3 = __ldg(ep + f4 + 65);
    float va[8] = {r0.x-e0.x, r0.y-e0.y, r0.z-e0.z, r0.w-e0.w,
                   r1.x-e1.x, r1.y-e1.y, r1.z-e1.z, r1.w-e1.w};
    float vb[8] = {r2.x-e2.x, r2.y-e2.y, r2.z-e2.z, r2.w-e2.w,
                   r3.x-e3.x, r3.y-e3.y, r3.z-e3.z, r3.w-e3.w};
    float lsum = 0.f;
    #pragma unroll
    for (int k = 0; k < 8; ++k) lsum += va[k]*va[k] + vb[k]*vb[k];

    if (outQ) {
        const float4* xp = (const float4*)(x + (size_t)row * DD);
        float4 x0 = __ldg(xp + f4), x1 = __ldg(xp + f4 + 1);
        float4 x2 = __ldg(xp + f4 + 64), x3 = __ldg(xp + f4 + 65);
        float4* op = (float4*)(outQ + (size_t)row * DD);
        op[f4]      = make_float4(x0.x-va[0], x0.y-va[1], x0.z-va[2], x0.w-va[3]);
        op[f4 + 1]  = make_float4(x1.x-va[4], x1.y-va[5], x1.z-va[6], x1.w-va[7]);
        op[f4 + 64] = make_float4(x2.x-vb[0], x2.y-vb[1], x2.z-vb[2], x2.w-vb[3]);
        op[f4 + 65] = make_float4(x3.x-vb[4], x3.y-vb[5], x3.z-vb[6], x3.w-vb[7]);
    } else {
        rp[f4]      = make_float4(va[0], va[1], va[2], va[3]);
        rp[f4 + 1]  = make_float4(va[4], va[5], va[6], va[7]);
        rp[f4 + 64] = make_float4(vb[0], vb[1], vb[2], vb[3]);
        rp[f4 + 65] = make_float4(vb[4], vb[5], vb[6], vb[7]);
        if (writeA) {
            uint4 ua, ub;
            pack_bf16_8(va, ua); pack_bf16_8(vb, ub);
            *(uint4*)(g_Abf + (size_t)row * DD + lane * 8)       = ua;
            *(uint4*)(g_Abf + (size_t)row * DD + 256 + lane * 8) = ub;
        }
    }
    #pragma unroll
    for (int m = 16; m > 0; m >>= 1) lsum += __shfl_xor_sync(0xffffffffu, lsum, m);
    return lsum;
}

// warp-cooperative resolve of one row (fast + inline exact rescore on global resid)
// then update. Bit-identical ids to the verified fast/slow pair.
static __device__ __forceinline__ void resolve_row(const float* __restrict__ cb,
                                                   const float* __restrict__ hn,
                                                   int row, int lane, int stage,
                                                   float* outIdxF, int writeA,
                                                   const float* __restrict__ x,
                                                   float* __restrict__ outQ) {
    const float* rrow = g_resid + (size_t)row * DD;
    const float4* rp = (const float4*)rrow;
    const int f4 = lane * 2;
    float4 r0 = rp[f4], r1 = rp[f4 + 1], r2 = rp[f4 + 64], r3 = rp[f4 + 65];

    int cnt = g_candcnt[row];
    int id;
    if (cnt <= CSLOTS) {
        unsigned long long mine = (lane < cnt) ? g_cand[(size_t)row * CSLOTS + lane] : 0ULL;
        unsigned long long mx = warpMaxU64(mine);
        float smax = keyScore(mx);
        bool surv = (lane < cnt) && (keyScore(mine) > smax - TAU);
        unsigned mask = __ballot_sync(0xffffffffu, surv);
        if (__popc(mask) == 1) {
            id = keyCode(mx);
        } else {
            unsigned long long myKey = 0ULL;
            if (surv) {
                int code = keyCode(mine);
                myKey = makeKey(exact_score(rrow, cb + (size_t)code * DD, hn[code]), code);
            }
            id = keyCode(warpMaxU64(myKey));
        }
    } else {
        unsigned long long bk = 0ULL;
        for (int c = lane; c < CC; c += 32) {
            unsigned long long k = makeKey(exact_score(rrow, cb + (size_t)c * DD, hn[c]), c);
            if (k > bk) bk = k;
        }
        id = keyCode(warpMaxU64(bk));
    }
    if (lane == 0) {
        g_candcnt[row] = 0;
        if (outIdxF) outIdxF[(size_t)row * QQ + stage] = (float)id;
    }
    float lsum = do_update(row, id, lane, cb, r0, r1, r2, r3, writeA, x, outQ);
    if (lane == 0) g_partial[(size_t)stage * MTOT + row] = lsum;
}

// ---------------- prep ----------------
__global__ void init_kernel(const float* __restrict__ x) {
    int gid = blockIdx.x * 256 + threadIdx.x;     // MTOT*64
    int row = gid >> 6, j = gid & 63;
    const float4* xp = (const float4*)(x + (size_t)row * DD + j * 8);
    float4 a = __ldg(xp), b = __ldg(xp + 1);
    float v[8] = {a.x,a.y,a.z,a.w,b.x,b.y,b.z,b.w};
    float4* rp = (float4*)(g_resid + (size_t)row * DD + j * 8);
    rp[0] = a; rp[1] = b;
    uint4 u; pack_bf16_8(v, u);
    *(uint4*)(g_Abf + (size_t)row * DD + j * 8) = u;
    if (j == 0) g_candcnt[row] = 0;
    if (gid < QQ * NTILES) g_done[gid] = 0;
    if (gid < QQ) g_qcnt[gid] = 0;
}

__global__ void convert_B(const float* __restrict__ cb) {
    int gid = blockIdx.x * 256 + threadIdx.x;     // QQ*CC*64
    int rowq = gid >> 6, j = gid & 63;            // rowq = q*CC+code
    const float4* e = (const float4*)(cb + (size_t)rowq * DD + j * 8);
    float4 a = __ldg(e), b = __ldg(e + 1);
    float v[8] = {a.x,a.y,a.z,a.w,b.x,b.y,b.z,b.w};
    uint4 u; pack_bf16_8(v, u);
    *(uint4*)(g_Bbf + (size_t)rowq * DD + j * 8) = u;
}

__global__ void halfnorm_kernel(const float* __restrict__ cb) {
    int code = blockIdx.x, t = threadIdx.x;
    const float4* e = (const float4*)(cb + (size_t)code * DD);
    float4 v = __ldg(&e[t]);
    float s = v.x*v.x + v.y*v.y + v.z*v.z + v.w*v.w;
    for (int m = 16; m > 0; m >>= 1) s += __shfl_xor_sync(0xffffffffu, s, m);
    __shared__ float red[4];
    if ((t & 31) == 0) red[t >> 5] = s;
    __syncthreads();
    if (t == 0) g_hn[code] = 0.5f * (red[0] + red[1] + red[2] + red[3]);
}

// ---------------- fused: resolve(stage-1) prologue + bf16 HMMA GEMM(stage) ------
// CTA: 128 rows x 128 codes, K=512 in 8 chunks of 64, double-buffered cp.async.
// grid = 512 rowTiles * 8 colTiles = 4096. GEMM body LOCKED at the 245us config.
// Prologue: each CTA resolves its own 16-row slice of the rowTile, then the 8
// sibling CTAs rendezvous on g_done before loading Abf.
__global__ __launch_bounds__(256, 2) void gemm_score(int stage, int resolveStage,
                                                     const float* __restrict__ cb_all,
                                                     float* outIdxF) {
    extern __shared__ unsigned char smdyn[];       // 2 * (16KB A + 16KB B)
    __shared__ unsigned s_t1[128];
    __shared__ float s_hn[128];

    const int tid = threadIdx.x, wid = tid >> 5, lane = tid & 31;
    const int colTile = blockIdx.x & 7, rowTile = blockIdx.x >> 3;
    const int rowBase = rowTile << 7, colBase = colTile << 7;
    const int mwarp = wid >> 2, nwarp = wid & 3;
    uint32_t smb = smem_u32(smdyn);

    if (resolveStage >= 0) {
        const float* rcb = cb_all + (size_t)resolveStage * CC * DD;
        const float* rhn = g_hn + resolveStage * CC;
        int sliceBase = rowBase + colTile * 16;
        #pragma unroll 1
        for (int r2 = 0; r2 < 2; ++r2)
            resolve_row(rcb, rhn, sliceBase + wid * 2 + r2, lane, resolveStage,
                        outIdxF, 1, nullptr, nullptr);
        __threadfence();
        __syncthreads();
        int* flag = &g_done[resolveStage * NTILES + rowTile];
        if (tid == 0) {
            atomicAdd(flag, 1);
            while (atomicAdd(flag, 0) < 8) __nanosleep(128);
        }
        __syncthreads();
    }

    const __nv_bfloat16* Ag = g_Abf;
    const __nv_bfloat16* Bg = g_Bbf + (size_t)stage * CC * DD;

    for (int i = tid; i < 128; i += 256) { s_t1[i] = 0u; s_hn[i] = g_hn[stage * CC + colBase + i]; }

    float d[4][4][4];
    #pragma unroll
    for (int a = 0; a < 4; ++a)
        #pragma unroll
        for (int b = 0; b < 4; ++b)
            #pragma unroll
            for (int c = 0; c < 4; ++c) d[a][b][c] = 0.f;

    const int kc = tid & 7;                        // constant 16B chunk per thread
    auto issue = [&](int chunk, int buf) {
        uint32_t sb = smb + (uint32_t)buf * 32768u;
        #pragma unroll
        for (int i = 0; i < 4; ++i) {
            int row = (tid >> 3) + i * 32;
            uint32_t sw = (uint32_t)((kc ^ (row & 7)) << 4);
            cp16(sb + (uint32_t)row * 128u + sw,
                 Ag + (size_t)(rowBase + row) * DD + chunk * 64 + kc * 8);
            cp16(sb + 16384u + (uint32_t)row * 128u + sw,
                 Bg + (size_t)(colBase + row) * DD + chunk * 64 + kc * 8);
        }
        asm volatile("cp.async.commit_group;" ::: "memory");
    };

    issue(0, 0);
    for (int ch = 0; ch < 8; ++ch) {
        if (ch < 7) { issue(ch + 1, (ch + 1) & 1); asm volatile("cp.async.wait_group 1;" ::: "memory"); }
        else        { asm volatile("cp.async.wait_group 0;" ::: "memory"); }
        __syncthreads();
        uint32_t ab = smb + (uint32_t)(ch & 1) * 32768u;
        uint32_t bb = ab + 16384u;
        #pragma unroll
        for (int s = 0; s < 4; ++s) {
            uint32_t afr[4][4], bfr[2][4];
            #pragma unroll
            for (int mf = 0; mf < 4; ++mf) {
                int r = mwarp * 64 + mf * 16 + (lane & 15);
                int k16 = s * 2 + (lane >> 4);
                LDSM4(afr[mf], ab + (uint32_t)r * 128u + (uint32_t)((k16 ^ (r & 7)) << 4));
            }
            #pragma unroll
            for (int np = 0; np < 2; ++np) {
                int cd = nwarp * 32 + np * 16 + ((lane & 16) >> 1) + (lane & 7);
                int k16 = s * 2 + ((lane >> 3) & 1);
                LDSM4(bfr[np], bb + (uint32_t)cd * 128u + (uint32_t)((k16 ^ (cd & 7)) << 4));
            }
            #pragma unroll
            for (int mf = 0; mf < 4; ++mf)
                #pragma unroll
                for (int nf = 0; nf < 4; ++nf)
                    MMA16816(d[mf][nf], afr[mf], bfr[nf >> 1][(nf & 1) * 2], bfr[nf >> 1][(nf & 1) * 2 + 1]);
        }
        __syncthreads();
    }

    // ---- epilogue: per-row tile max, then emit candidates within TAU of it ----
    float rtop[4][2];
    #pragma unroll
    for (int mf = 0; mf < 4; ++mf)
        #pragma unroll
        for (int h = 0; h < 2; ++h) {
            float best = -3.0e38f;
            #pragma unroll
            for (int nf = 0; nf < 4; ++nf)
                #pragma unroll
                for (int q = 0; q < 2; ++q) {
                    int col = nwarp * 32 + nf * 8 + (lane & 3) * 2 + q;
                    best = fmaxf(best, d[mf][nf][h * 2 + q] - s_hn[col]);
                }
            rtop[mf][h] = best;
        }
    #pragma unroll
    for (int m = 1; m <= 2; m <<= 1)
        #pragma unroll
        for (int mf = 0; mf < 4; ++mf)
            #pragma unroll
            for (int h = 0; h < 2; ++h)
                rtop[mf][h] = fmaxf(rtop[mf][h], __shfl_xor_sync(0xffffffffu, rtop[mf][h], m));
    if ((lane & 3) == 0) {
        #pragma unroll
        for (int mf = 0; mf < 4; ++mf)
            #pragma unroll
            for (int h = 0; h < 2; ++h)
                atomicMax(&s_t1[mwarp * 64 + mf * 16 + h * 8 + (lane >> 2)], fkey(rtop[mf][h]));
    }
    __syncthreads();
    #pragma unroll
    for (int mf = 0; mf < 4; ++mf)
        #pragma unroll
        for (int h = 0; h < 2; ++h) {
            int lrow = mwarp * 64 + mf * 16 + h * 8 + (lane >> 2);
            float thr = unfkey(s_t1[lrow]) - TAU;
            int grow = rowBase + lrow;
            #pragma unroll
            for (int nf = 0; nf < 4; ++nf)
                #pragma unroll
                for (int q = 0; q < 2; ++q) {
                    int col = nwarp * 32 + nf * 8 + (lane & 3) * 2 + q;
                    float v = d[mf][nf][h * 2 + q] - s_hn[col];
                    if (v > thr) {
                        int p = atomicAdd(&g_candcnt[grow], 1);
                        if (p < CSLOTS) g_cand[(size_t)grow * CSLOTS + p] = makeKey(v, colBase + col);
                    }
                }
        }
}

// ---------------- stage-7 standalone resolve (fast + slow queue) ----------------
__global__ __launch_bounds__(256) void resolve_fast(const float* __restrict__ cb_all, int stage,
                                                    float* outIdxF, int writeA,
                                                    const float* __restrict__ x,
                                                    float* __restrict__ outQ) {
    const int wid = threadIdx.x >> 5, lane = threadIdx.x & 31;
    const int row = blockIdx.x * 8 + wid;
    const float* cb = cb_all + (size_t)stage * CC * DD;

    float4* rp = (float4*)(g_resid + (size_t)row * DD);
    const int f4 = lane * 2;
    float4 r0 = rp[f4], r1 = rp[f4 + 1], r2 = rp[f4 + 64], r3 = rp[f4 + 65];

    int cnt = g_candcnt[row];
    int id = -1;
    if (cnt <= CSLOTS) {
        unsigned long long mine = (lane < cnt) ? g_cand[(size_t)row * CSLOTS + lane] : 0ULL;
        unsigned long long mx = warpMaxU64(mine);
        float smax = keyScore(mx);
        bool surv = (lane < cnt) && (keyScore(mine) > smax - TAU);
        unsigned mask = __ballot_sync(0xffffffffu, surv);
        if (__popc(mask) == 1) id = keyCode(mx);
    }
    if (id < 0) {
        if (lane == 0) {
            int p = atomicAdd(&g_qcnt[stage], 1);
            g_queue[p] = row;
        }
        return;
    }
    if (lane == 0) {
        g_candcnt[row] = 0;
        if (outIdxF) outIdxF[(size_t)row * QQ + stage] = (float)id;
    }
    float lsum = do_update(row, id, lane, cb, r0, r1, r2, r3, writeA, x, outQ);
    if (lane == 0) g_partial[(size_t)stage * MTOT + row] = lsum;
}

__global__ __launch_bounds__(256) void resolve_slow(const float* __restrict__ cb_all, int stage,
                                                    float* outIdxF, int writeA,
                                                    const float* __restrict__ x,
                                                    float* __restrict__ outQ) {
    const int wid = threadIdx.x >> 5, lane = threadIdx.x & 31;
    const float* cb = cb_all + (size_t)stage * CC * DD;
    const float* hn = g_hn + stage * CC;
    const int total = g_qcnt[stage];
    const int f4 = lane * 2;

    for (int i = blockIdx.x * 8 + wid; i < total; i += gridDim.x * 8) {
        int row = g_queue[i];
        const float* rrow = g_resid + (size_t)row * DD;
        const float4* rp = (const float4*)rrow;
        float4 r0 = rp[f4], r1 = rp[f4 + 1], r2 = rp[f4 + 64], r3 = rp[f4 + 65];

        int cnt = g_candcnt[row];
        int id;
        if (cnt <= CSLOTS) {
            unsigned long long mine = (lane < cnt) ? g_cand[(size_t)row * CSLOTS + lane] : 0ULL;
            unsigned long long mx = warpMaxU64(mine);
            float smax = keyScore(mx);
            bool surv = (lane < cnt) && (keyScore(mine) > smax - TAU);
            unsigned mask = __ballot_sync(0xffffffffu, surv);
            if (__popc(mask) == 1) {
                id = keyCode(mx);
            } else {
                unsigned long long myKey = 0ULL;
                if (surv) {
                    int code = keyCode(mine);
                    myKey = makeKey(exact_score(rrow, cb + (size_t)code * DD, hn[code]), code);
                }
                id = keyCode(warpMaxU64(myKey));
            }
        } else {
            unsigned long long bk = 0ULL;
            for (int c = lane; c < CC; c += 32) {
                unsigned long long k = makeKey(exact_score(rrow, cb + (size_t)c * DD, hn[c]), c);
                if (k > bk) bk = k;
            }
            id = keyCode(warpMaxU64(bk));
        }
        if (lane == 0) {
            g_candcnt[row] = 0;
            if (outIdxF) outIdxF[(size_t)row * QQ + stage] = (float)id;
        }
        float lsum = do_update(row, id, lane, cb, r0, r1, r2, r3, writeA, x, outQ);
        if (lane == 0) g_partial[(size_t)stage * MTOT + row] = lsum;
        __syncwarp();
    }
}

// ---------------- losses: 8-way parallel per-stage reduction (same order) ------
__global__ void losses_partial() {
    __shared__ float red[256];
    int q = blockIdx.x, tid = threadIdx.x;
    float s = 0.f;
    for (int i = tid; i < MTOT; i += 256) s += g_partial[(size_t)q * MTOT + i];
    red[tid] = s;
    __syncthreads();
    for (int st = 128; st > 0; st >>= 1) {
        if (tid < st) red[tid] += red[tid + st];
        __syncthreads();
    }
    if (tid == 0) g_stageLoss[q] = red[0] * (COMMIT_W / ((float)MTOT * (float)DD));
}
__global__ void losses_final(float* outLoss, float* outFinal) {
    if (threadIdx.x == 0) {
        float tot = 0.f;
        for (int q = 0; q < QQ; ++q) {
            float v = g_stageLoss[q];
            if (outLoss) outLoss[q] = v;
            tot += v;
        }
        if (outFinal) *outFinal = tot;
    }
}

__global__ void finalize_kernel(const float* __restrict__ x, float* __restrict__ out, size_t n) {
    size_t i = (size_t)blockIdx.x * blockDim.x + threadIdx.x;
    if (i < n) out[i] = x[i] - g_resid[i];
}
__global__ void zero_tail(float* out, size_t start, size_t end) {
    size_t i = start + (size_t)blockIdx.x * blockDim.x + threadIdx.x;
    if (i < end) out[i] = 0.f;
}

// ---------------- launch ----------------
extern "C" void kernel_launch(void* const* d_in, const int* in_sizes, int n_in,
                              void* d_out, int out_size) {
    const float* x  = (const float*)d_in[0];
    const float* cb = (const float*)d_in[1];
    if (n_in >= 2 && in_sizes[0] == QQ * CC * DD && in_sizes[1] == (int)MD) {
        x = (const float*)d_in[1]; cb = (const float*)d_in[0];
    }
    cudaFuncSetAttribute(gemm_score, cudaFuncAttributeMaxDynamicSharedMemorySize, 65536);

    float* out = (float*)d_out;
    const size_t offI = MD, offL = offI + (size_t)MTOT * QQ, offF = offL + QQ, tot = offF + 1;
    size_t osz = (size_t)out_size;
    float* outIdxF  = (osz >= offL) ? out + offI : nullptr;
    float* outLoss  = (osz >= offF) ? out + offL : nullptr;
    float* outFinal = (osz >= tot)  ? out + offF : nullptr;
    bool fuseFinal = (osz >= MD);

    init_kernel<<<MTOT / 4, 256>>>(x);
    convert_B<<<QQ * CC / 4, 256>>>(cb);
    halfnorm_kernel<<<QQ * CC, 128>>>(cb);

    for (int q = 0; q < QQ; ++q)
        gemm_score<<<4096, 256, 65536>>>(q, q - 1, cb, outIdxF);

    // stage 7 resolve (fused final output)
    {
        float* oq = fuseFinal ? out : nullptr;
        resolve_fast<<<MTOT / 8, 256>>>(cb, QQ - 1, outIdxF, 0, x, oq);
        resolve_slow<<<512, 256>>>(cb, QQ - 1, outIdxF, 0, x, oq);
    }
    losses_partial<<<QQ, 256>>>();
    losses_final<<<1, 32>>>(outLoss, outFinal);

    if (!fuseFinal && osz > 0)
        finalize_kernel<<<(unsigned)((osz + 255) / 256), 256>>>(x, out, osz);
    if (osz > tot)
        zero_tail<<<(unsigned)((osz - tot + 255) / 256), 256>>>(out, tot, osz);
}

// round 15
// speedup vs baseline: 1.0032x; 1.0032x over previous
#include <cuda_runtime.h>
#include <cuda_bf16.h>
#include <cstdint>

#define DD 512
#define QQ 8
#define CC 1024
#define MTOT 65536
#define MD ((size_t)MTOT*DD)
#define COMMIT_W 0.02f
#define TAU 2.0f
#define CSLOTS 32
#define NTILES 512

// ---------------- device scratch (no cudaMalloc allowed) ----------------
__device__ __align__(128) float g_resid[MD];                       // fp32 residual
__device__ __align__(128) __nv_bfloat16 g_Abf[MD];                 // bf16 residual
__device__ __align__(128) __nv_bfloat16 g_Bbf[(size_t)QQ*CC*DD];   // bf16 codebooks
__device__ float g_hn[QQ*CC];                                      // exact 0.5*||e||^2
__device__ float g_partial[(size_t)QQ*MTOT];                       // per-row loss parts
__device__ float g_stageLoss[QQ];
__device__ int   g_candcnt[MTOT];
__device__ unsigned long long g_cand[(size_t)MTOT*CSLOTS];
__device__ int   g_done[QQ*NTILES];                                // per-tile arrival tickets

// ---------------- helpers ----------------
static __device__ __forceinline__ uint32_t smem_u32(const void* p) {
    uint32_t a;
    asm("{ .reg .u64 t; cvta.to.shared.u64 t, %1; cvt.u32.u64 %0, t; }" : "=r"(a) : "l"(p));
    return a;
}
static __device__ __forceinline__ unsigned fkey(float s) {
    unsigned u = __float_as_uint(s);
    return (u & 0x80000000u) ? ~u : (u | 0x80000000u);
}
static __device__ __forceinline__ float unfkey(unsigned u) {
    return (u & 0x80000000u) ? __uint_as_float(u & 0x7FFFFFFFu) : __uint_as_float(~u);
}
// key orders by score desc, then LOWEST code (matches jnp.argmin tie-break)
static __device__ __forceinline__ unsigned long long makeKey(float s, int c) {
    return ((unsigned long long)fkey(s) << 32) | (unsigned)(0xFFFFFFFFu - (unsigned)c);
}
static __device__ __forceinline__ int   keyCode(unsigned long long k) { return (int)(0xFFFFFFFFu - (unsigned)(k & 0xFFFFFFFFu)); }
static __device__ __forceinline__ float keyScore(unsigned long long k) { return unfkey((unsigned)(k >> 32)); }
static __device__ __forceinline__ unsigned long long warpMaxU64(unsigned long long v) {
    #pragma unroll
    for (int m = 16; m > 0; m >>= 1) {
        unsigned long long o = __shfl_xor_sync(0xffffffffu, v, m);
        if (o > v) v = o;
    }
    return v;
}

#define LDSM4(R, addr) asm volatile( \
    "ldmatrix.sync.aligned.m8n8.x4.shared.b16 {%0,%1,%2,%3}, [%4];" \
    : "=r"((R)[0]),"=r"((R)[1]),"=r"((R)[2]),"=r"((R)[3]) : "r"(addr))

#define MMA16816(D, A, b0, b1) asm volatile( \
    "mma.sync.aligned.m16n8k16.row.col.f32.bf16.bf16.f32 " \
    "{%0,%1,%2,%3},{%4,%5,%6,%7},{%8,%9},{%0,%1,%2,%3};" \
    : "+f"((D)[0]),"+f"((D)[1]),"+f"((D)[2]),"+f"((D)[3]) \
    : "r"((A)[0]),"r"((A)[1]),"r"((A)[2]),"r"((A)[3]),"r"(b0),"r"(b1))

static __device__ __forceinline__ void cp16(uint32_t saddr, const void* gptr) {
    asm volatile("cp.async.cg.shared.global [%0], [%1], 16;"
                 :: "r"(saddr), "l"(__cvta_generic_to_global(gptr)));
}
static __device__ __forceinline__ void pack_bf16_8(const float* v, uint4& u) {
    unsigned h[8];
    #pragma unroll
    for (int i = 0; i < 8; ++i) {
        __nv_bfloat16 b = __float2bfloat16_rn(v[i]);
        h[i] = *(unsigned short*)&b;
    }
    u.x = h[0]|(h[1]<<16); u.y = h[2]|(h[3]<<16); u.z = h[4]|(h[5]<<16); u.w = h[6]|(h[7]<<16);
}
// R1-bit-exact score: sequential fp32 FMA over k ascending (float4 loads, scalar
// FMA order identical to the verified scalar version), minus exact hn.
static __device__ __forceinline__ float exact_score(const float* __restrict__ rr,
                                                    const float* __restrict__ e,
                                                    float hnv) {
    const float4* e4 = (const float4*)e;
    const float4* r4 = (const float4*)rr;
    float dot = 0.f;
    #pragma unroll 8
    for (int k = 0; k < DD / 4; ++k) {
        float4 ev = __ldg(&e4[k]);
        float4 rv = __ldg(&r4[k]);
        dot = __fmaf_rn(rv.x, ev.x, dot);
        dot = __fmaf_rn(rv.y, ev.y, dot);
        dot = __fmaf_rn(rv.z, ev.z, dot);
        dot = __fmaf_rn(rv.w, ev.w, dot);
    }
    return dot - hnv;
}

// shared update body: computes v = r - e, writes resid/Abf or final out, returns lsum
static __device__ __forceinline__ float do_update(int row, int id, int lane,
                                                  const float* __restrict__ cb,
                                                  float4 r0, float4 r1, float4 r2, float4 r3,
                                                  int writeA,
                                                  const float* __restrict__ x,
                                                  float* __restrict__ outQ) {
    float4* rp = (float4*)(g_resid + (size_t)row * DD);
    const int f4 = lane * 2;
    const float4* ep = (const float4*)(cb + (size_t)id * DD);
    float4 e0 = __ldg(ep + f4), e1 = __ldg(ep + f4 + 1);
    float4 e2 = __ldg(ep + f4 + 64), e3 = __ldg(ep + f4 + 65);
    float va[8] = {r0.x-e0.x, r0.y-e0.y, r0.z-e0.z, r0.w-e0.w,
                   r1.x-e1.x, r1.y-e1.y, r1.z-e1.z, r1.w-e1.w};
    float vb[8] = {r2.x-e2.x, r2.y-e2.y, r2.z-e2.z, r2.w-e2.w,
                   r3.x-e3.x, r3.y-e3.y, r3.z-e3.z, r3.w-e3.w};
    float lsum = 0.f;
    #pragma unroll
    for (int k = 0; k < 8; ++k) lsum += va[k]*va[k] + vb[k]*vb[k];

    if (outQ) {
        const float4* xp = (const float4*)(x + (size_t)row * DD);
        float4 x0 = __ldg(xp + f4), x1 = __ldg(xp + f4 + 1);
        float4 x2 = __ldg(xp + f4 + 64), x3 = __ldg(xp + f4 + 65);
        float4* op = (float4*)(outQ + (size_t)row * DD);
        op[f4]      = make_float4(x0.x-va[0], x0.y-va[1], x0.z-va[2], x0.w-va[3]);
        op[f4 + 1]  = make_float4(x1.x-va[4], x1.y-va[5], x1.z-va[6], x1.w-va[7]);
        op[f4 + 64] = make_float4(x2.x-vb[0], x2.y-vb[1], x2.z-vb[2], x2.w-vb[3]);
        op[f4 + 65] = make_float4(x3.x-vb[4], x3.y-vb[5], x3.z-vb[6], x3.w-vb[7]);
    } else {
        rp[f4]      = make_float4(va[0], va[1], va[2], va[3]);
        rp[f4 + 1]  = make_float4(va[4], va[5], va[6], va[7]);
        rp[f4 + 64] = make_float4(vb[0], vb[1], vb[2], vb[3]);
        rp[f4 + 65] = make_float4(vb[4], vb[5], vb[6], vb[7]);
        if (writeA) {
            uint4 ua, ub;
            pack_bf16_8(va, ua); pack_bf16_8(vb, ub);
            *(uint4*)(g_Abf + (size_t)row * DD + lane * 8)       = ua;
            *(uint4*)(g_Abf + (size_t)row * DD + 256 + lane * 8) = ub;
        }
    }
    #pragma unroll
    for (int m = 16; m > 0; m >>= 1) lsum += __shfl_xor_sync(0xffffffffu, lsum, m);
    return lsum;
}

// warp-cooperative resolve of one row (fast + inline exact rescore on global resid)
// then update. Bit-identical ids to the verified fast/slow pair (validated in R14).
static __device__ __forceinline__ void resolve_row(const float* __restrict__ cb,
                                                   const float* __restrict__ hn,
                                                   int row, int lane, int stage,
                                                   float* outIdxF, int writeA,
                                                   const float* __restrict__ x,
                                                   float* __restrict__ outQ) {
    const float* rrow = g_resid + (size_t)row * DD;
    const float4* rp = (const float4*)rrow;
    const int f4 = lane * 2;
    float4 r0 = rp[f4], r1 = rp[f4 + 1], r2 = rp[f4 + 64], r3 = rp[f4 + 65];

    int cnt = g_candcnt[row];
    int id;
    if (cnt <= CSLOTS) {
        unsigned long long mine = (lane < cnt) ? g_cand[(size_t)row * CSLOTS + lane] : 0ULL;
        unsigned long long mx = warpMaxU64(mine);
        float smax = keyScore(mx);
        bool surv = (lane < cnt) && (keyScore(mine) > smax - TAU);
        unsigned mask = __ballot_sync(0xffffffffu, surv);
        if (__popc(mask) == 1) {
            id = keyCode(mx);
        } else {
            unsigned long long myKey = 0ULL;
            if (surv) {
                int code = keyCode(mine);
                myKey = makeKey(exact_score(rrow, cb + (size_t)code * DD, hn[code]), code);
            }
            id = keyCode(warpMaxU64(myKey));
        }
    } else {
        unsigned long long bk = 0ULL;
        for (int c = lane; c < CC; c += 32) {
            unsigned long long k = makeKey(exact_score(rrow, cb + (size_t)c * DD, hn[c]), c);
            if (k > bk) bk = k;
        }
        id = keyCode(warpMaxU64(bk));
    }
    if (lane == 0) {
        g_candcnt[row] = 0;
        if (outIdxF) outIdxF[(size_t)row * QQ + stage] = (float)id;
    }
    float lsum = do_update(row, id, lane, cb, r0, r1, r2, r3, writeA, x, outQ);
    if (lane == 0) g_partial[(size_t)stage * MTOT + row] = lsum;
}

// ---------------- prep ----------------
__global__ void init_kernel(const float* __restrict__ x) {
    int gid = blockIdx.x * 256 + threadIdx.x;     // MTOT*64
    int row = gid >> 6, j = gid & 63;
    const float4* xp = (const float4*)(x + (size_t)row * DD + j * 8);
    float4 a = __ldg(xp), b = __ldg(xp + 1);
    float v[8] = {a.x,a.y,a.z,a.w,b.x,b.y,b.z,b.w};
    float4* rp = (float4*)(g_resid + (size_t)row * DD + j * 8);
    rp[0] = a; rp[1] = b;
    uint4 u; pack_bf16_8(v, u);
    *(uint4*)(g_Abf + (size_t)row * DD + j * 8) = u;
    if (j == 0) g_candcnt[row] = 0;
    if (gid < QQ * NTILES) g_done[gid] = 0;       // replay-safe ticket reset
}

__global__ void convert_B(const float* __restrict__ cb) {
    int gid = blockIdx.x * 256 + threadIdx.x;     // QQ*CC*64
    int rowq = gid >> 6, j = gid & 63;            // rowq = q*CC+code
    const float4* e = (const float4*)(cb + (size_t)rowq * DD + j * 8);
    float4 a = __ldg(e), b = __ldg(e + 1);
    float v[8] = {a.x,a.y,a.z,a.w,b.x,b.y,b.z,b.w};
    uint4 u; pack_bf16_8(v, u);
    *(uint4*)(g_Bbf + (size_t)rowq * DD + j * 8) = u;
}

__global__ void halfnorm_kernel(const float* __restrict__ cb) {
    int code = blockIdx.x, t = threadIdx.x;
    const float4* e = (const float4*)(cb + (size_t)code * DD);
    float4 v = __ldg(&e[t]);
    float s = v.x*v.x + v.y*v.y + v.z*v.z + v.w*v.w;
    for (int m = 16; m > 0; m >>= 1) s += __shfl_xor_sync(0xffffffffu, s, m);
    __shared__ float red[4];
    if ((t & 31) == 0) red[t >> 5] = s;
    __syncthreads();
    if (t == 0) g_hn[code] = 0.5f * (red[0] + red[1] + red[2] + red[3]);
}

// ---------------- bf16 HMMA GEMM + candidate emission + ticket-resolve ----------
// CTA: 128 rows x 128 codes, K=512 in 8 chunks of 64, double-buffered cp.async.
// grid = 512 rowTiles * 8 colTiles = 4096. GEMM body LOCKED at the 245us config.
// Epilogue: after candidate emission each CTA takes a ticket; the LAST of the 8
// sibling CTAs (rank==7) resolves all 128 rows of the tile inline (no spinning).
__global__ __launch_bounds__(256, 2) void gemm_score(int stage,
                                                     const float* __restrict__ cb_all,
                                                     float* outIdxF, int writeA,
                                                     const float* __restrict__ x,
                                                     float* __restrict__ outQ) {
    extern __shared__ unsigned char smdyn[];       // 2 * (16KB A + 16KB B)
    __shared__ unsigned s_t1[128];
    __shared__ float s_hn[128];
    __shared__ int s_rank;

    const int tid = threadIdx.x, wid = tid >> 5, lane = tid & 31;
    const int colTile = blockIdx.x & 7, rowTile = blockIdx.x >> 3;
    const int rowBase = rowTile << 7, colBase = colTile << 7;
    const int mwarp = wid >> 2, nwarp = wid & 3;
    uint32_t smb = smem_u32(smdyn);
    const __nv_bfloat16* Ag = g_Abf;
    const __nv_bfloat16* Bg = g_Bbf + (size_t)stage * CC * DD;

    for (int i = tid; i < 128; i += 256) { s_t1[i] = 0u; s_hn[i] = g_hn[stage * CC + colBase + i]; }

    float d[4][4][4];
    #pragma unroll
    for (int a = 0; a < 4; ++a)
        #pragma unroll
        for (int b = 0; b < 4; ++b)
            #pragma unroll
            for (int c = 0; c < 4; ++c) d[a][b][c] = 0.f;

    const int kc = tid & 7;                        // constant 16B chunk per thread
    auto issue = [&](int chunk, int buf) {
        uint32_t sb = smb + (uint32_t)buf * 32768u;
        #pragma unroll
        for (int i = 0; i < 4; ++i) {
            int row = (tid >> 3) + i * 32;
            uint32_t sw = (uint32_t)((kc ^ (row & 7)) << 4);
            cp16(sb + (uint32_t)row * 128u + sw,
                 Ag + (size_t)(rowBase + row) * DD + chunk * 64 + kc * 8);
            cp16(sb + 16384u + (uint32_t)row * 128u + sw,
                 Bg + (size_t)(colBase + row) * DD + chunk * 64 + kc * 8);
        }
        asm volatile("cp.async.commit_group;" ::: "memory");
    };

    issue(0, 0);
    for (int ch = 0; ch < 8; ++ch) {
        if (ch < 7) { issue(ch + 1, (ch + 1) & 1); asm volatile("cp.async.wait_group 1;" ::: "memory"); }
        else        { asm volatile("cp.async.wait_group 0;" ::: "memory"); }
        __syncthreads();
        uint32_t ab = smb + (uint32_t)(ch & 1) * 32768u;
        uint32_t bb = ab + 16384u;
        #pragma unroll
        for (int s = 0; s < 4; ++s) {
            uint32_t afr[4][4], bfr[2][4];
            #pragma unroll
            for (int mf = 0; mf < 4; ++mf) {
                int r = mwarp * 64 + mf * 16 + (lane & 15);
                int k16 = s * 2 + (lane >> 4);
                LDSM4(afr[mf], ab + (uint32_t)r * 128u + (uint32_t)((k16 ^ (r & 7)) << 4));
            }
            #pragma unroll
            for (int np = 0; np < 2; ++np) {
                int cd = nwarp * 32 + np * 16 + ((lane & 16) >> 1) + (lane & 7);
                int k16 = s * 2 + ((lane >> 3) & 1);
                LDSM4(bfr[np], bb + (uint32_t)cd * 128u + (uint32_t)((k16 ^ (cd & 7)) << 4));
            }
            #pragma unroll
            for (int mf = 0; mf < 4; ++mf)
                #pragma unroll
                for (int nf = 0; nf < 4; ++nf)
                    MMA16816(d[mf][nf], afr[mf], bfr[nf >> 1][(nf & 1) * 2], bfr[nf >> 1][(nf & 1) * 2 + 1]);
        }
        __syncthreads();
    }

    // ---- epilogue: per-row tile max, then emit candidates within TAU of it ----
    float rtop[4][2];
    #pragma unroll
    for (int mf = 0; mf < 4; ++mf)
        #pragma unroll
        for (int h = 0; h < 2; ++h) {
            float best = -3.0e38f;
            #pragma unroll
            for (int nf = 0; nf < 4; ++nf)
                #pragma unroll
                for (int q = 0; q < 2; ++q) {
                    int col = nwarp * 32 + nf * 8 + (lane & 3) * 2 + q;
                    best = fmaxf(best, d[mf][nf][h * 2 + q] - s_hn[col]);
                }
            rtop[mf][h] = best;
        }
    #pragma unroll
    for (int m = 1; m <= 2; m <<= 1)
        #pragma unroll
        for (int mf = 0; mf < 4; ++mf)
            #pragma unroll
            for (int h = 0; h < 2; ++h)
                rtop[mf][h] = fmaxf(rtop[mf][h], __shfl_xor_sync(0xffffffffu, rtop[mf][h], m));
    if ((lane & 3) == 0) {
        #pragma unroll
        for (int mf = 0; mf < 4; ++mf)
            #pragma unroll
            for (int h = 0; h < 2; ++h)
                atomicMax(&s_t1[mwarp * 64 + mf * 16 + h * 8 + (lane >> 2)], fkey(rtop[mf][h]));
    }
    __syncthreads();
    #pragma unroll
    for (int mf = 0; mf < 4; ++mf)
        #pragma unroll
        for (int h = 0; h < 2; ++h) {
            int lrow = mwarp * 64 + mf * 16 + h * 8 + (lane >> 2);
            float thr = unfkey(s_t1[lrow]) - TAU;
            int grow = rowBase + lrow;
            #pragma unroll
            for (int nf = 0; nf < 4; ++nf)
                #pragma unroll
                for (int q = 0; q < 2; ++q) {
                    int col = nwarp * 32 + nf * 8 + (lane & 3) * 2 + q;
                    float v = d[mf][nf][h * 2 + q] - s_hn[col];
                    if (v > thr) {
                        int p = atomicAdd(&g_candcnt[grow], 1);
                        if (p < CSLOTS) g_cand[(size_t)grow * CSLOTS + p] = makeKey(v, colBase + col);
                    }
                }
        }

    // ---- ticket: last CTA of this rowTile resolves all 128 rows ----
    __threadfence();
    __syncthreads();
    if (tid == 0) s_rank = atomicAdd(&g_done[stage * NTILES + rowTile], 1);
    __syncthreads();
    if (s_rank == 7) {
        const float* cbf = cb_all + (size_t)stage * CC * DD;
        const float* hn = g_hn + stage * CC;
        #pragma unroll 1
        for (int r = 0; r < 16; ++r)
            resolve_row(cbf, hn, rowBase + wid * 16 + r, lane, stage,
                        outIdxF, writeA, x, outQ);
    }
}

// ---------------- losses: 8-way parallel per-stage reduction (same order) ------
__global__ void losses_partial() {
    __shared__ float red[256];
    int q = blockIdx.x, tid = threadIdx.x;
    float s = 0.f;
    for (int i = tid; i < MTOT; i += 256) s += g_partial[(size_t)q * MTOT + i];
    red[tid] = s;
    __syncthreads();
    for (int st = 128; st > 0; st >>= 1) {
        if (tid < st) red[tid] += red[tid + st];
        __syncthreads();
    }
    if (tid == 0) g_stageLoss[q] = red[0] * (COMMIT_W / ((float)MTOT * (float)DD));
}
__global__ void losses_final(float* outLoss, float* outFinal) {
    if (threadIdx.x == 0) {
        float tot = 0.f;
        for (int q = 0; q < QQ; ++q) {
            float v = g_stageLoss[q];
            if (outLoss) outLoss[q] = v;
            tot += v;
        }
        if (outFinal) *outFinal = tot;
    }
}

__global__ void finalize_kernel(const float* __restrict__ x, float* __restrict__ out, size_t n) {
    size_t i = (size_t)blockIdx.x * blockDim.x + threadIdx.x;
    if (i < n) out[i] = x[i] - g_resid[i];
}
__global__ void zero_tail(float* out, size_t start, size_t end) {
    size_t i = start + (size_t)blockIdx.x * blockDim.x + threadIdx.x;
    if (i < end) out[i] = 0.f;
}

// ---------------- launch ----------------
extern "C" void kernel_launch(void* const* d_in, const int* in_sizes, int n_in,
                              void* d_out, int out_size) {
    const float* x  = (const float*)d_in[0];
    const float* cb = (const float*)d_in[1];
    if (n_in >= 2 && in_sizes[0] == QQ * CC * DD && in_sizes[1] == (int)MD) {
        x = (const float*)d_in[1]; cb = (const float*)d_in[0];
    }
    cudaFuncSetAttribute(gemm_score, cudaFuncAttributeMaxDynamicSharedMemorySize, 65536);

    float* out = (float*)d_out;
    const size_t offI = MD, offL = offI + (size_t)MTOT * QQ, offF = offL + QQ, tot = offF + 1;
    size_t osz = (size_t)out_size;
    float* outIdxF  = (osz >= offL) ? out + offI : nullptr;
    float* outLoss  = (osz >= offF) ? out + offL : nullptr;
    float* outFinal = (osz >= tot)  ? out + offF : nullptr;
    bool fuseFinal = (osz >= MD);

    init_kernel<<<MTOT / 4, 256>>>(x);
    convert_B<<<QQ * CC / 4, 256>>>(cb);
    halfnorm_kernel<<<QQ * CC, 128>>>(cb);

    for (int q = 0; q < QQ; ++q) {
        bool last = (q == QQ - 1);
        float* oq = (last && fuseFinal) ? out : nullptr;
        gemm_score<<<4096, 256, 65536>>>(q, cb, outIdxF, last ? 0 : 1, x, oq);
    }
    losses_partial<<<QQ, 256>>>();
    losses_final<<<1, 32>>>(outLoss, outFinal);

    if (!fuseFinal && osz > 0)
        finalize_kernel<<<(unsigned)((osz + 255) / 256), 256>>>(x, out, osz);
    if (osz > tot)
        zero_tail<<<(unsigned)((osz - tot + 255) / 256), 256>>>(out, tot, osz);
}

// round 16
// speedup vs baseline: 1.2723x; 1.2682x over previous
#include <cuda_runtime.h>
#include <cuda_bf16.h>
#include <cstdint>

#define DD 512
#define QQ 8
#define CC 1024
#define MTOT 65536
#define MD ((size_t)MTOT*DD)
#define COMMIT_W 0.02f
#define TAU 2.0f
#define CSLOTS 32

// ---------------- device scratch (no cudaMalloc allowed) ----------------
__device__ __align__(128) float g_resid[MD];                       // fp32 residual
__device__ __align__(128) __nv_bfloat16 g_Abf[MD];                 // bf16 residual
__device__ __align__(128) __nv_bfloat16 g_Bbf[(size_t)QQ*CC*DD];   // bf16 codebooks
__device__ float g_hn[QQ*CC];                                      // exact 0.5*||e||^2
__device__ float g_partial[(size_t)QQ*MTOT];                       // per-row loss parts
__device__ float g_stageLoss[QQ];
__device__ int   g_candcnt[MTOT];
__device__ unsigned long long g_cand[(size_t)MTOT*CSLOTS];

// ---------------- helpers ----------------
static __device__ __forceinline__ uint32_t smem_u32(const void* p) {
    uint32_t a;
    asm("{ .reg .u64 t; cvta.to.shared.u64 t, %1; cvt.u32.u64 %0, t; }" : "=r"(a) : "l"(p));
    return a;
}
static __device__ __forceinline__ unsigned fkey(float s) {
    unsigned u = __float_as_uint(s);
    return (u & 0x80000000u) ? ~u : (u | 0x80000000u);
}
static __device__ __forceinline__ float unfkey(unsigned u) {
    return (u & 0x80000000u) ? __uint_as_float(u & 0x7FFFFFFFu) : __uint_as_float(~u);
}
// key orders by score desc, then LOWEST code (matches jnp.argmin tie-break)
static __device__ __forceinline__ unsigned long long makeKey(float s, int c) {
    return ((unsigned long long)fkey(s) << 32) | (unsigned)(0xFFFFFFFFu - (unsigned)c);
}
static __device__ __forceinline__ int   keyCode(unsigned long long k) { return (int)(0xFFFFFFFFu - (unsigned)(k & 0xFFFFFFFFu)); }
static __device__ __forceinline__ float keyScore(unsigned long long k) { return unfkey((unsigned)(k >> 32)); }
static __device__ __forceinline__ unsigned long long warpMaxU64(unsigned long long v) {
    #pragma unroll
    for (int m = 16; m > 0; m >>= 1) {
        unsigned long long o = __shfl_xor_sync(0xffffffffu, v, m);
        if (o > v) v = o;
    }
    return v;
}

#define LDSM4(R, addr) asm volatile( \
    "ldmatrix.sync.aligned.m8n8.x4.shared.b16 {%0,%1,%2,%3}, [%4];" \
    : "=r"((R)[0]),"=r"((R)[1]),"=r"((R)[2]),"=r"((R)[3]) : "r"(addr))

#define MMA16816(D, A, b0, b1) asm volatile( \
    "mma.sync.aligned.m16n8k16.row.col.f32.bf16.bf16.f32 " \
    "{%0,%1,%2,%3},{%4,%5,%6,%7},{%8,%9},{%0,%1,%2,%3};" \
    : "+f"((D)[0]),"+f"((D)[1]),"+f"((D)[2]),"+f"((D)[3]) \
    : "r"((A)[0]),"r"((A)[1]),"r"((A)[2]),"r"((A)[3]),"r"(b0),"r"(b1))

static __device__ __forceinline__ void cp16(uint32_t saddr, const void* gptr) {
    asm volatile("cp.async.cg.shared.global [%0], [%1], 16;"
                 :: "r"(saddr), "l"(__cvta_generic_to_global(gptr)));
}
static __device__ __forceinline__ void pack_bf16_8(const float* v, uint4& u) {
    unsigned h[8];
    #pragma unroll
    for (int i = 0; i < 8; ++i) {
        __nv_bfloat16 b = __float2bfloat16_rn(v[i]);
        h[i] = *(unsigned short*)&b;
    }
    u.x = h[0]|(h[1]<<16); u.y = h[2]|(h[3]<<16); u.z = h[4]|(h[5]<<16); u.w = h[6]|(h[7]<<16);
}
// R1-bit-exact score: sequential fp32 FMA over k ascending (float4 loads, scalar
// FMA order identical to the verified scalar version), minus exact hn.
static __device__ __forceinline__ float exact_score(const float* __restrict__ rr,
                                                    const float* __restrict__ e,
                                                    float hnv) {
    const float4* e4 = (const float4*)e;
    const float4* r4 = (const float4*)rr;
    float dot = 0.f;
    #pragma unroll 8
    for (int k = 0; k < DD / 4; ++k) {
        float4 ev = __ldg(&e4[k]);
        float4 rv = __ldg(&r4[k]);
        dot = __fmaf_rn(rv.x, ev.x, dot);
        dot = __fmaf_rn(rv.y, ev.y, dot);
        dot = __fmaf_rn(rv.z, ev.z, dot);
        dot = __fmaf_rn(rv.w, ev.w, dot);
    }
    return dot - hnv;
}

// shared update body: computes v = r - e, writes resid/Abf or final out, returns lsum
static __device__ __forceinline__ float do_update(int row, int id, int lane,
                                                  const float* __restrict__ cb,
                                                  float4 r0, float4 r1, float4 r2, float4 r3,
                                                  int writeA,
                                                  const float* __restrict__ x,
                                                  float* __restrict__ outQ) {
    float4* rp = (float4*)(g_resid + (size_t)row * DD);
    const int f4 = lane * 2;
    const float4* ep = (const float4*)(cb + (size_t)id * DD);
    float4 e0 = __ldg(ep + f4), e1 = __ldg(ep + f4 + 1);
    float4 e2 = __ldg(ep + f4 + 64), e3 = __ldg(ep + f4 + 65);
    float va[8] = {r0.x-e0.x, r0.y-e0.y, r0.z-e0.z, r0.w-e0.w,
                   r1.x-e1.x, r1.y-e1.y, r1.z-e1.z, r1.w-e1.w};
    float vb[8] = {r2.x-e2.x, r2.y-e2.y, r2.z-e2.z, r2.w-e2.w,
                   r3.x-e3.x, r3.y-e3.y, r3.z-e3.z, r3.w-e3.w};
    float lsum = 0.f;
    #pragma unroll
    for (int k = 0; k < 8; ++k) lsum += va[k]*va[k] + vb[k]*vb[k];

    if (outQ) {
        const float4* xp = (const float4*)(x + (size_t)row * DD);
        float4 x0 = __ldg(xp + f4), x1 = __ldg(xp + f4 + 1);
        float4 x2 = __ldg(xp + f4 + 64), x3 = __ldg(xp + f4 + 65);
        float4* op = (float4*)(outQ + (size_t)row * DD);
        op[f4]      = make_float4(x0.x-va[0], x0.y-va[1], x0.z-va[2], x0.w-va[3]);
        op[f4 + 1]  = make_float4(x1.x-va[4], x1.y-va[5], x1.z-va[6], x1.w-va[7]);
        op[f4 + 64] = make_float4(x2.x-vb[0], x2.y-vb[1], x2.z-vb[2], x2.w-vb[3]);
        op[f4 + 65] = make_float4(x3.x-vb[4], x3.y-vb[5], x3.z-vb[6], x3.w-vb[7]);
    } else {
        rp[f4]      = make_float4(va[0], va[1], va[2], va[3]);
        rp[f4 + 1]  = make_float4(va[4], va[5], va[6], va[7]);
        rp[f4 + 64] = make_float4(vb[0], vb[1], vb[2], vb[3]);
        rp[f4 + 65] = make_float4(vb[4], vb[5], vb[6], vb[7]);
        if (writeA) {
            uint4 ua, ub;
            pack_bf16_8(va, ua); pack_bf16_8(vb, ub);
            *(uint4*)(g_Abf + (size_t)row * DD + lane * 8)       = ua;
            *(uint4*)(g_Abf + (size_t)row * DD + 256 + lane * 8) = ub;
        }
    }
    #pragma unroll
    for (int m = 16; m > 0; m >>= 1) lsum += __shfl_xor_sync(0xffffffffu, lsum, m);
    return lsum;
}

// ---------------- prep ----------------
__global__ void init_kernel(const float* __restrict__ x) {
    int gid = blockIdx.x * 256 + threadIdx.x;     // MTOT*64
    int row = gid >> 6, j = gid & 63;
    const float4* xp = (const float4*)(x + (size_t)row * DD + j * 8);
    float4 a = __ldg(xp), b = __ldg(xp + 1);
    float v[8] = {a.x,a.y,a.z,a.w,b.x,b.y,b.z,b.w};
    float4* rp = (float4*)(g_resid + (size_t)row * DD + j * 8);
    rp[0] = a; rp[1] = b;
    uint4 u; pack_bf16_8(v, u);
    *(uint4*)(g_Abf + (size_t)row * DD + j * 8) = u;
    if (j == 0) g_candcnt[row] = 0;
}

__global__ void convert_B(const float* __restrict__ cb) {
    int gid = blockIdx.x * 256 + threadIdx.x;     // QQ*CC*64
    int rowq = gid >> 6, j = gid & 63;            // rowq = q*CC+code
    const float4* e = (const float4*)(cb + (size_t)rowq * DD + j * 8);
    float4 a = __ldg(e), b = __ldg(e + 1);
    float v[8] = {a.x,a.y,a.z,a.w,b.x,b.y,b.z,b.w};
    uint4 u; pack_bf16_8(v, u);
    *(uint4*)(g_Bbf + (size_t)rowq * DD + j * 8) = u;
}

__global__ void halfnorm_kernel(const float* __restrict__ cb) {
    int code = blockIdx.x, t = threadIdx.x;
    const float4* e = (const float4*)(cb + (size_t)code * DD);
    float4 v = __ldg(&e[t]);
    float s = v.x*v.x + v.y*v.y + v.z*v.z + v.w*v.w;
    for (int m = 16; m > 0; m >>= 1) s += __shfl_xor_sync(0xffffffffu, s, m);
    __shared__ float red[4];
    if ((t & 31) == 0) red[t >> 5] = s;
    __syncthreads();
    if (t == 0) g_hn[code] = 0.5f * (red[0] + red[1] + red[2] + red[3]);
}

// ---------------- bf16 HMMA GEMM + per-row candidate emission ----------------
// CTA: 128 rows x 128 codes, K=512 in 8 chunks of 64, double-buffered cp.async.
// grid = 512 rowTiles * 8 colTiles = 4096.  (the proven 245us configuration - LOCKED)
__global__ __launch_bounds__(256, 2) void gemm_score(int stage) {
    extern __shared__ unsigned char smdyn[];       // 2 * (16KB A + 16KB B)
    __shared__ unsigned s_t1[128];
    __shared__ float s_hn[128];

    const int tid = threadIdx.x, wid = tid >> 5, lane = tid & 31;
    const int colTile = blockIdx.x & 7, rowTile = blockIdx.x >> 3;
    const int rowBase = rowTile << 7, colBase = colTile << 7;
    const int mwarp = wid >> 2, nwarp = wid & 3;
    uint32_t smb = smem_u32(smdyn);
    const __nv_bfloat16* Ag = g_Abf;
    const __nv_bfloat16* Bg = g_Bbf + (size_t)stage * CC * DD;

    for (int i = tid; i < 128; i += 256) { s_t1[i] = 0u; s_hn[i] = g_hn[stage * CC + colBase + i]; }

    float d[4][4][4];
    #pragma unroll
    for (int a = 0; a < 4; ++a)
        #pragma unroll
        for (int b = 0; b < 4; ++b)
            #pragma unroll
            for (int c = 0; c < 4; ++c) d[a][b][c] = 0.f;

    const int kc = tid & 7;                        // constant 16B chunk per thread
    auto issue = [&](int chunk, int buf) {
        uint32_t sb = smb + (uint32_t)buf * 32768u;
        #pragma unroll
        for (int i = 0; i < 4; ++i) {
            int row = (tid >> 3) + i * 32;
            uint32_t sw = (uint32_t)((kc ^ (row & 7)) << 4);
            cp16(sb + (uint32_t)row * 128u + sw,
                 Ag + (size_t)(rowBase + row) * DD + chunk * 64 + kc * 8);
            cp16(sb + 16384u + (uint32_t)row * 128u + sw,
                 Bg + (size_t)(colBase + row) * DD + chunk * 64 + kc * 8);
        }
        asm volatile("cp.async.commit_group;" ::: "memory");
    };

    issue(0, 0);
    for (int ch = 0; ch < 8; ++ch) {
        if (ch < 7) { issue(ch + 1, (ch + 1) & 1); asm volatile("cp.async.wait_group 1;" ::: "memory"); }
        else        { asm volatile("cp.async.wait_group 0;" ::: "memory"); }
        __syncthreads();
        uint32_t ab = smb + (uint32_t)(ch & 1) * 32768u;
        uint32_t bb = ab + 16384u;
        #pragma unroll
        for (int s = 0; s < 4; ++s) {
            uint32_t afr[4][4], bfr[2][4];
            #pragma unroll
            for (int mf = 0; mf < 4; ++mf) {
                int r = mwarp * 64 + mf * 16 + (lane & 15);
                int k16 = s * 2 + (lane >> 4);
                LDSM4(afr[mf], ab + (uint32_t)r * 128u + (uint32_t)((k16 ^ (r & 7)) << 4));
            }
            #pragma unroll
            for (int np = 0; np < 2; ++np) {
                int cd = nwarp * 32 + np * 16 + ((lane & 16) >> 1) + (lane & 7);
                int k16 = s * 2 + ((lane >> 3) & 1);
                LDSM4(bfr[np], bb + (uint32_t)cd * 128u + (uint32_t)((k16 ^ (cd & 7)) << 4));
            }
            #pragma unroll
            for (int mf = 0; mf < 4; ++mf)
                #pragma unroll
                for (int nf = 0; nf < 4; ++nf)
                    MMA16816(d[mf][nf], afr[mf], bfr[nf >> 1][(nf & 1) * 2], bfr[nf >> 1][(nf & 1) * 2 + 1]);
        }
        __syncthreads();
    }

    // ---- epilogue: per-row tile max, then emit candidates within TAU of it ----
    float rtop[4][2];
    #pragma unroll
    for (int mf = 0; mf < 4; ++mf)
        #pragma unroll
        for (int h = 0; h < 2; ++h) {
            float best = -3.0e38f;
            #pragma unroll
            for (int nf = 0; nf < 4; ++nf)
                #pragma unroll
                for (int q = 0; q < 2; ++q) {
                    int col = nwarp * 32 + nf * 8 + (lane & 3) * 2 + q;
                    best = fmaxf(best, d[mf][nf][h * 2 + q] - s_hn[col]);
                }
            rtop[mf][h] = best;
        }
    #pragma unroll
    for (int m = 1; m <= 2; m <<= 1)
        #pragma unroll
        for (int mf = 0; mf < 4; ++mf)
            #pragma unroll
            for (int h = 0; h < 2; ++h)
                rtop[mf][h] = fmaxf(rtop[mf][h], __shfl_xor_sync(0xffffffffu, rtop[mf][h], m));
    if ((lane & 3) == 0) {
        #pragma unroll
        for (int mf = 0; mf < 4; ++mf)
            #pragma unroll
            for (int h = 0; h < 2; ++h)
                atomicMax(&s_t1[mwarp * 64 + mf * 16 + h * 8 + (lane >> 2)], fkey(rtop[mf][h]));
    }
    __syncthreads();
    #pragma unroll
    for (int mf = 0; mf < 4; ++mf)
        #pragma unroll
        for (int h = 0; h < 2; ++h) {
            int lrow = mwarp * 64 + mf * 16 + h * 8 + (lane >> 2);
            float thr = unfkey(s_t1[lrow]) - TAU;
            int grow = rowBase + lrow;
            #pragma unroll
            for (int nf = 0; nf < 4; ++nf)
                #pragma unroll
                for (int q = 0; q < 2; ++q) {
                    int col = nwarp * 32 + nf * 8 + (lane & 3) * 2 + q;
                    float v = d[mf][nf][h * 2 + q] - s_hn[col];
                    if (v > thr) {
                        int p = atomicAdd(&g_candcnt[grow], 1);
                        if (p < CSLOTS) g_cand[(size_t)grow * CSLOTS + p] = makeKey(v, colBase + col);
                    }
                }
        }
}

// ---------------- single-pass resolve + update (inline exact rescore) ----------
// Warp per row, no smem, no block syncs. Exact path validated bit-exact (R14/R15).
__global__ __launch_bounds__(256) void resolve_update(const float* __restrict__ cb_all, int stage,
                                                      float* outIdxF, int writeA,
                                                      const float* __restrict__ x,
                                                      float* __restrict__ outQ) {
    const int wid = threadIdx.x >> 5, lane = threadIdx.x & 31;
    const int row = blockIdx.x * 8 + wid;
    const float* cb = cb_all + (size_t)stage * CC * DD;
    const float* hn = g_hn + stage * CC;
    const float* rrow = g_resid + (size_t)row * DD;

    // hoisted: independent of resolve outcome
    const float4* rp = (const float4*)rrow;
    const int f4 = lane * 2;
    float4 r0 = rp[f4], r1 = rp[f4 + 1], r2 = rp[f4 + 64], r3 = rp[f4 + 65];

    int cnt = g_candcnt[row];
    int id;
    if (cnt <= CSLOTS) {
        unsigned long long mine = (lane < cnt) ? g_cand[(size_t)row * CSLOTS + lane] : 0ULL;
        unsigned long long mx = warpMaxU64(mine);
        float smax = keyScore(mx);
        bool surv = (lane < cnt) && (keyScore(mine) > smax - TAU);
        unsigned mask = __ballot_sync(0xffffffffu, surv);
        if (__popc(mask) == 1) {
            id = keyCode(mx);
        } else {
            unsigned long long myKey = 0ULL;
            if (surv) {
                int code = keyCode(mine);
                myKey = makeKey(exact_score(rrow, cb + (size_t)code * DD, hn[code]), code);
            }
            id = keyCode(warpMaxU64(myKey));
        }
    } else {
        unsigned long long bk = 0ULL;
        for (int c = lane; c < CC; c += 32) {
            unsigned long long k = makeKey(exact_score(rrow, cb + (size_t)c * DD, hn[c]), c);
            if (k > bk) bk = k;
        }
        id = keyCode(warpMaxU64(bk));
    }
    if (lane == 0) {
        g_candcnt[row] = 0;                        // reset for next stage
        if (outIdxF) outIdxF[(size_t)row * QQ + stage] = (float)id;
    }
    float lsum = do_update(row, id, lane, cb, r0, r1, r2, r3, writeA, x, outQ);
    if (lane == 0) g_partial[(size_t)stage * MTOT + row] = lsum;
}

// ---------------- losses: 8-way parallel per-stage reduction (same order) ------
__global__ void losses_partial() {
    __shared__ float red[256];
    int q = blockIdx.x, tid = threadIdx.x;
    float s = 0.f;
    for (int i = tid; i < MTOT; i += 256) s += g_partial[(size_t)q * MTOT + i];
    red[tid] = s;
    __syncthreads();
    for (int st = 128; st > 0; st >>= 1) {
        if (tid < st) red[tid] += red[tid + st];
        __syncthreads();
    }
    if (tid == 0) g_stageLoss[q] = red[0] * (COMMIT_W / ((float)MTOT * (float)DD));
}
__global__ void losses_final(float* outLoss, float* outFinal) {
    if (threadIdx.x == 0) {
        float tot = 0.f;
        for (int q = 0; q < QQ; ++q) {
            float v = g_stageLoss[q];
            if (outLoss) outLoss[q] = v;
            tot += v;
        }
        if (outFinal) *outFinal = tot;
    }
}

__global__ void finalize_kernel(const float* __restrict__ x, float* __restrict__ out, size_t n) {
    size_t i = (size_t)blockIdx.x * blockDim.x + threadIdx.x;
    if (i < n) out[i] = x[i] - g_resid[i];
}
__global__ void zero_tail(float* out, size_t start, size_t end) {
    size_t i = start + (size_t)blockIdx.x * blockDim.x + threadIdx.x;
    if (i < end) out[i] = 0.f;
}

// ---------------- launch ----------------
extern "C" void kernel_launch(void* const* d_in, const int* in_sizes, int n_in,
                              void* d_out, int out_size) {
    const float* x  = (const float*)d_in[0];
    const float* cb = (const float*)d_in[1];
    if (n_in >= 2 && in_sizes[0] == QQ * CC * DD && in_sizes[1] == (int)MD) {
        x = (const float*)d_in[1]; cb = (const float*)d_in[0];
    }
    cudaFuncSetAttribute(gemm_score, cudaFuncAttributeMaxDynamicSharedMemorySize, 65536);

    float* out = (float*)d_out;
    const size_t offI = MD, offL = offI + (size_t)MTOT * QQ, offF = offL + QQ, tot = offF + 1;
    size_t osz = (size_t)out_size;
    float* outIdxF  = (osz >= offL) ? out + offI : nullptr;
    float* outLoss  = (osz >= offF) ? out + offL : nullptr;
    float* outFinal = (osz >= tot)  ? out + offF : nullptr;
    bool fuseFinal = (osz >= MD);

    init_kernel<<<MTOT / 4, 256>>>(x);
    convert_B<<<QQ * CC / 4, 256>>>(cb);
    halfnorm_kernel<<<QQ * CC, 128>>>(cb);

    for (int q = 0; q < QQ; ++q) {
        gemm_score<<<4096, 256, 65536>>>(q);
        bool last = (q == QQ - 1);
        float* oq = (last && fuseFinal) ? out : nullptr;
        resolve_update<<<MTOT / 8, 256>>>(cb, q, outIdxF, last ? 0 : 1, x, oq);
    }
    losses_partial<<<QQ, 256>>>();
    losses_final<<<1, 32>>>(outLoss, outFinal);

    if (!fuseFinal && osz > 0)
        finalize_kernel<<<(unsigned)((osz + 255) / 256), 256>>>(x, out, osz);
    if (osz > tot)
        zero_tail<<<(unsigned)((osz - tot + 255) / 256), 256>>>(out, tot, osz);
}

// round 17
// speedup vs baseline: 1.2871x; 1.0117x over previous
#include <cuda_runtime.h>
#include <cuda_bf16.h>
#include <cstdint>

#define DD 512
#define QQ 8
#define CC 1024
#define MTOT 65536
#define MD ((size_t)MTOT*DD)
#define COMMIT_W 0.02f
#define TAU 2.0f
#define CSLOTS 32

// ---------------- device scratch (no cudaMalloc allowed) ----------------
__device__ __align__(128) float g_resid[MD];                       // fp32 residual
__device__ __align__(128) __nv_bfloat16 g_Abf[MD];                 // bf16 residual
__device__ __align__(128) __nv_bfloat16 g_Bbf[(size_t)QQ*CC*DD];   // bf16 codebooks
__device__ float g_hn[QQ*CC];                                      // exact 0.5*||e||^2
__device__ float g_partial[(size_t)QQ*MTOT];                       // per-row loss parts
__device__ float g_stageLoss[QQ];
__device__ int   g_candcnt[MTOT];
__device__ unsigned long long g_cand[(size_t)MTOT*CSLOTS];

// ---------------- helpers ----------------
static __device__ __forceinline__ uint32_t smem_u32(const void* p) {
    uint32_t a;
    asm("{ .reg .u64 t; cvta.to.shared.u64 t, %1; cvt.u32.u64 %0, t; }" : "=r"(a) : "l"(p));
    return a;
}
static __device__ __forceinline__ unsigned fkey(float s) {
    unsigned u = __float_as_uint(s);
    return (u & 0x80000000u) ? ~u : (u | 0x80000000u);
}
static __device__ __forceinline__ float unfkey(unsigned u) {
    return (u & 0x80000000u) ? __uint_as_float(u & 0x7FFFFFFFu) : __uint_as_float(~u);
}
// key orders by score desc, then LOWEST code (matches jnp.argmin tie-break)
static __device__ __forceinline__ unsigned long long makeKey(float s, int c) {
    return ((unsigned long long)fkey(s) << 32) | (unsigned)(0xFFFFFFFFu - (unsigned)c);
}
static __device__ __forceinline__ int   keyCode(unsigned long long k) { return (int)(0xFFFFFFFFu - (unsigned)(k & 0xFFFFFFFFu)); }
static __device__ __forceinline__ float keyScore(unsigned long long k) { return unfkey((unsigned)(k >> 32)); }
static __device__ __forceinline__ unsigned long long warpMaxU64(unsigned long long v) {
    #pragma unroll
    for (int m = 16; m > 0; m >>= 1) {
        unsigned long long o = __shfl_xor_sync(0xffffffffu, v, m);
        if (o > v) v = o;
    }
    return v;
}

#define LDSM4(R, addr) asm volatile( \
    "ldmatrix.sync.aligned.m8n8.x4.shared.b16 {%0,%1,%2,%3}, [%4];" \
    : "=r"((R)[0]),"=r"((R)[1]),"=r"((R)[2]),"=r"((R)[3]) : "r"(addr))

#define MMA16816(D, A, b0, b1) asm volatile( \
    "mma.sync.aligned.m16n8k16.row.col.f32.bf16.bf16.f32 " \
    "{%0,%1,%2,%3},{%4,%5,%6,%7},{%8,%9},{%0,%1,%2,%3};" \
    : "+f"((D)[0]),"+f"((D)[1]),"+f"((D)[2]),"+f"((D)[3]) \
    : "r"((A)[0]),"r"((A)[1]),"r"((A)[2]),"r"((A)[3]),"r"(b0),"r"(b1))

static __device__ __forceinline__ void cp16(uint32_t saddr, const void* gptr) {
    asm volatile("cp.async.cg.shared.global [%0], [%1], 16;"
                 :: "r"(saddr), "l"(__cvta_generic_to_global(gptr)));
}
static __device__ __forceinline__ void pack_bf16_8(const float* v, uint4& u) {
    unsigned h[8];
    #pragma unroll
    for (int i = 0; i < 8; ++i) {
        __nv_bfloat16 b = __float2bfloat16_rn(v[i]);
        h[i] = *(unsigned short*)&b;
    }
    u.x = h[0]|(h[1]<<16); u.y = h[2]|(h[3]<<16); u.z = h[4]|(h[5]<<16); u.w = h[6]|(h[7]<<16);
}
// R1-bit-exact score: sequential fp32 FMA over k ascending (float4 loads, scalar
// FMA order identical to the verified scalar version), minus exact hn.
static __device__ __forceinline__ float exact_score(const float* __restrict__ rr,
                                                    const float* __restrict__ e,
                                                    float hnv) {
    const float4* e4 = (const float4*)e;
    const float4* r4 = (const float4*)rr;
    float dot = 0.f;
    #pragma unroll 8
    for (int k = 0; k < DD / 4; ++k) {
        float4 ev = __ldg(&e4[k]);
        float4 rv = __ldg(&r4[k]);
        dot = __fmaf_rn(rv.x, ev.x, dot);
        dot = __fmaf_rn(rv.y, ev.y, dot);
        dot = __fmaf_rn(rv.z, ev.z, dot);
        dot = __fmaf_rn(rv.w, ev.w, dot);
    }
    return dot - hnv;
}

// shared update body: computes v = r - e, writes resid/Abf or final out, returns lsum
static __device__ __forceinline__ float do_update(int row, int id, int lane,
                                                  const float* __restrict__ cb,
                                                  float4 r0, float4 r1, float4 r2, float4 r3,
                                                  int writeA,
                                                  const float* __restrict__ x,
                                                  float* __restrict__ outQ) {
    float4* rp = (float4*)(g_resid + (size_t)row * DD);
    const int f4 = lane * 2;
    const float4* ep = (const float4*)(cb + (size_t)id * DD);
    float4 e0 = __ldg(ep + f4), e1 = __ldg(ep + f4 + 1);
    float4 e2 = __ldg(ep + f4 + 64), e3 = __ldg(ep + f4 + 65);
    float va[8] = {r0.x-e0.x, r0.y-e0.y, r0.z-e0.z, r0.w-e0.w,
                   r1.x-e1.x, r1.y-e1.y, r1.z-e1.z, r1.w-e1.w};
    float vb[8] = {r2.x-e2.x, r2.y-e2.y, r2.z-e2.z, r2.w-e2.w,
                   r3.x-e3.x, r3.y-e3.y, r3.z-e3.z, r3.w-e3.w};
    float lsum = 0.f;
    #pragma unroll
    for (int k = 0; k < 8; ++k) lsum += va[k]*va[k] + vb[k]*vb[k];

    if (outQ) {
        const float4* xp = (const float4*)(x + (size_t)row * DD);
        float4 x0 = __ldg(xp + f4), x1 = __ldg(xp + f4 + 1);
        float4 x2 = __ldg(xp + f4 + 64), x3 = __ldg(xp + f4 + 65);
        float4* op = (float4*)(outQ + (size_t)row * DD);
        op[f4]      = make_float4(x0.x-va[0], x0.y-va[1], x0.z-va[2], x0.w-va[3]);
        op[f4 + 1]  = make_float4(x1.x-va[4], x1.y-va[5], x1.z-va[6], x1.w-va[7]);
        op[f4 + 64] = make_float4(x2.x-vb[0], x2.y-vb[1], x2.z-vb[2], x2.w-vb[3]);
        op[f4 + 65] = make_float4(x3.x-vb[4], x3.y-vb[5], x3.z-vb[6], x3.w-vb[7]);
    } else {
        rp[f4]      = make_float4(va[0], va[1], va[2], va[3]);
        rp[f4 + 1]  = make_float4(va[4], va[5], va[6], va[7]);
        rp[f4 + 64] = make_float4(vb[0], vb[1], vb[2], vb[3]);
        rp[f4 + 65] = make_float4(vb[4], vb[5], vb[6], vb[7]);
        if (writeA) {
            uint4 ua, ub;
            pack_bf16_8(va, ua); pack_bf16_8(vb, ub);
            *(uint4*)(g_Abf + (size_t)row * DD + lane * 8)       = ua;
            *(uint4*)(g_Abf + (size_t)row * DD + 256 + lane * 8) = ub;
        }
    }
    #pragma unroll
    for (int m = 16; m > 0; m >>= 1) lsum += __shfl_xor_sync(0xffffffffu, lsum, m);
    return lsum;
}

// ---------------- prep ----------------
__global__ void init_kernel(const float* __restrict__ x) {
    int gid = blockIdx.x * 256 + threadIdx.x;     // MTOT*64
    int row = gid >> 6, j = gid & 63;
    const float4* xp = (const float4*)(x + (size_t)row * DD + j * 8);
    float4 a = __ldg(xp), b = __ldg(xp + 1);
    float v[8] = {a.x,a.y,a.z,a.w,b.x,b.y,b.z,b.w};
    float4* rp = (float4*)(g_resid + (size_t)row * DD + j * 8);
    rp[0] = a; rp[1] = b;
    uint4 u; pack_bf16_8(v, u);
    *(uint4*)(g_Abf + (size_t)row * DD + j * 8) = u;
    if (j == 0) g_candcnt[row] = 0;
}

__global__ void convert_B(const float* __restrict__ cb) {
    int gid = blockIdx.x * 256 + threadIdx.x;     // QQ*CC*64
    int rowq = gid >> 6, j = gid & 63;            // rowq = q*CC+code
    const float4* e = (const float4*)(cb + (size_t)rowq * DD + j * 8);
    float4 a = __ldg(e), b = __ldg(e + 1);
    float v[8] = {a.x,a.y,a.z,a.w,b.x,b.y,b.z,b.w};
    uint4 u; pack_bf16_8(v, u);
    *(uint4*)(g_Bbf + (size_t)rowq * DD + j * 8) = u;
}

__global__ void halfnorm_kernel(const float* __restrict__ cb) {
    int code = blockIdx.x, t = threadIdx.x;
    const float4* e = (const float4*)(cb + (size_t)code * DD);
    float4 v = __ldg(&e[t]);
    float s = v.x*v.x + v.y*v.y + v.z*v.z + v.w*v.w;
    for (int m = 16; m > 0; m >>= 1) s += __shfl_xor_sync(0xffffffffu, s, m);
    __shared__ float red[4];
    if ((t & 31) == 0) red[t >> 5] = s;
    __syncthreads();
    if (t == 0) g_hn[code] = 0.5f * (red[0] + red[1] + red[2] + red[3]);
}

// ---------------- bf16 HMMA GEMM + per-row candidate emission ----------------
// CTA: 128 rows x 128 codes, K=512 in 8 chunks of 64, double-buffered cp.async.
// grid = 512 rowTiles * 8 colTiles = 4096.  (the proven 245us configuration - LOCKED)
// PDL: sync before touching Abf/candidates; trigger as the last statement.
__global__ __launch_bounds__(256, 2) void gemm_score(int stage) {
    extern __shared__ unsigned char smdyn[];       // 2 * (16KB A + 16KB B)
    __shared__ unsigned s_t1[128];
    __shared__ float s_hn[128];

    const int tid = threadIdx.x, wid = tid >> 5, lane = tid & 31;
    const int colTile = blockIdx.x & 7, rowTile = blockIdx.x >> 3;
    const int rowBase = rowTile << 7, colBase = colTile << 7;
    const int mwarp = wid >> 2, nwarp = wid & 3;
    uint32_t smb = smem_u32(smdyn);
    const __nv_bfloat16* Ag = g_Abf;
    const __nv_bfloat16* Bg = g_Bbf + (size_t)stage * CC * DD;

    // pre-sync: shared-mem-only init (no dependence on upstream kernel)
    for (int i = tid; i < 128; i += 256) s_t1[i] = 0u;

    cudaGridDependencySynchronize();               // upstream resolve/halfnorm done

    for (int i = tid; i < 128; i += 256) s_hn[i] = g_hn[stage * CC + colBase + i];

    float d[4][4][4];
    #pragma unroll
    for (int a = 0; a < 4; ++a)
        #pragma unroll
        for (int b = 0; b < 4; ++b)
            #pragma unroll
            for (int c = 0; c < 4; ++c) d[a][b][c] = 0.f;

    const int kc = tid & 7;                        // constant 16B chunk per thread
    auto issue = [&](int chunk, int buf) {
        uint32_t sb = smb + (uint32_t)buf * 32768u;
        #pragma unroll
        for (int i = 0; i < 4; ++i) {
            int row = (tid >> 3) + i * 32;
            uint32_t sw = (uint32_t)((kc ^ (row & 7)) << 4);
            cp16(sb + (uint32_t)row * 128u + sw,
                 Ag + (size_t)(rowBase + row) * DD + chunk * 64 + kc * 8);
            cp16(sb + 16384u + (uint32_t)row * 128u + sw,
                 Bg + (size_t)(colBase + row) * DD + chunk * 64 + kc * 8);
        }
        asm volatile("cp.async.commit_group;" ::: "memory");
    };

    issue(0, 0);
    for (int ch = 0; ch < 8; ++ch) {
        if (ch < 7) { issue(ch + 1, (ch + 1) & 1); asm volatile("cp.async.wait_group 1;" ::: "memory"); }
        else        { asm volatile("cp.async.wait_group 0;" ::: "memory"); }
        __syncthreads();
        uint32_t ab = smb + (uint32_t)(ch & 1) * 32768u;
        uint32_t bb = ab + 16384u;
        #pragma unroll
        for (int s = 0; s < 4; ++s) {
            uint32_t afr[4][4], bfr[2][4];
            #pragma unroll
            for (int mf = 0; mf < 4; ++mf) {
                int r = mwarp * 64 + mf * 16 + (lane & 15);
                int k16 = s * 2 + (lane >> 4);
                LDSM4(afr[mf], ab + (uint32_t)r * 128u + (uint32_t)((k16 ^ (r & 7)) << 4));
            }
            #pragma unroll
            for (int np = 0; np < 2; ++np) {
                int cd = nwarp * 32 + np * 16 + ((lane & 16) >> 1) + (lane & 7);
                int k16 = s * 2 + ((lane >> 3) & 1);
                LDSM4(bfr[np], bb + (uint32_t)cd * 128u + (uint32_t)((k16 ^ (cd & 7)) << 4));
            }
            #pragma unroll
            for (int mf = 0; mf < 4; ++mf)
                #pragma unroll
                for (int nf = 0; nf < 4; ++nf)
                    MMA16816(d[mf][nf], afr[mf], bfr[nf >> 1][(nf & 1) * 2], bfr[nf >> 1][(nf & 1) * 2 + 1]);
        }
        __syncthreads();
    }

    // ---- epilogue: per-row tile max, then emit candidates within TAU of it ----
    float rtop[4][2];
    #pragma unroll
    for (int mf = 0; mf < 4; ++mf)
        #pragma unroll
        for (int h = 0; h < 2; ++h) {
            float best = -3.0e38f;
            #pragma unroll
            for (int nf = 0; nf < 4; ++nf)
                #pragma unroll
                for (int q = 0; q < 2; ++q) {
                    int col = nwarp * 32 + nf * 8 + (lane & 3) * 2 + q;
                    best = fmaxf(best, d[mf][nf][h * 2 + q] - s_hn[col]);
                }
            rtop[mf][h] = best;
        }
    #pragma unroll
    for (int m = 1; m <= 2; m <<= 1)
        #pragma unroll
        for (int mf = 0; mf < 4; ++mf)
            #pragma unroll
            for (int h = 0; h < 2; ++h)
                rtop[mf][h] = fmaxf(rtop[mf][h], __shfl_xor_sync(0xffffffffu, rtop[mf][h], m));
    if ((lane & 3) == 0) {
        #pragma unroll
        for (int mf = 0; mf < 4; ++mf)
            #pragma unroll
            for (int h = 0; h < 2; ++h)
                atomicMax(&s_t1[mwarp * 64 + mf * 16 + h * 8 + (lane >> 2)], fkey(rtop[mf][h]));
    }
    __syncthreads();
    #pragma unroll
    for (int mf = 0; mf < 4; ++mf)
        #pragma unroll
        for (int h = 0; h < 2; ++h) {
            int lrow = mwarp * 64 + mf * 16 + h * 8 + (lane >> 2);
            float thr = unfkey(s_t1[lrow]) - TAU;
            int grow = rowBase + lrow;
            #pragma unroll
            for (int nf = 0; nf < 4; ++nf)
                #pragma unroll
                for (int q = 0; q < 2; ++q) {
                    int col = nwarp * 32 + nf * 8 + (lane & 3) * 2 + q;
                    float v = d[mf][nf][h * 2 + q] - s_hn[col];
                    if (v > thr) {
                        int p = atomicAdd(&g_candcnt[grow], 1);
                        if (p < CSLOTS) g_cand[(size_t)grow * CSLOTS + p] = makeKey(v, colBase + col);
                    }
                }
        }

    cudaTriggerProgrammaticLaunchCompletion();     // all writes done; let resolve start
}

// ---------------- single-pass resolve + update (inline exact rescore) ----------
// Warp per row, no smem, no block syncs. PDL: resid preload pre-sync (gemm never
// writes resid), then sync before reading candidates. Trigger last.
__global__ __launch_bounds__(256) void resolve_update(const float* __restrict__ cb_all, int stage,
                                                      float* outIdxF, int writeA,
                                                      const float* __restrict__ x,
                                                      float* __restrict__ outQ) {
    const int wid = threadIdx.x >> 5, lane = threadIdx.x & 31;
    const int row = blockIdx.x * 8 + wid;
    const float* cb = cb_all + (size_t)stage * CC * DD;
    const float* hn = g_hn + stage * CC;
    const float* rrow = g_resid + (size_t)row * DD;

    // pre-sync: resid loads (not written by the concurrent gemm)
    const float4* rp = (const float4*)rrow;
    const int f4 = lane * 2;
    float4 r0 = rp[f4], r1 = rp[f4 + 1], r2 = rp[f4 + 64], r3 = rp[f4 + 65];

    cudaGridDependencySynchronize();               // gemm's candidates now visible

    int cnt = g_candcnt[row];
    int id;
    if (cnt <= CSLOTS) {
        unsigned long long mine = (lane < cnt) ? g_cand[(size_t)row * CSLOTS + lane] : 0ULL;
        unsigned long long mx = warpMaxU64(mine);
        float smax = keyScore(mx);
        bool surv = (lane < cnt) && (keyScore(mine) > smax - TAU);
        unsigned mask = __ballot_sync(0xffffffffu, surv);
        if (__popc(mask) == 1) {
            id = keyCode(mx);
        } else {
            unsigned long long myKey = 0ULL;
            if (surv) {
                int code = keyCode(mine);
                myKey = makeKey(exact_score(rrow, cb + (size_t)code * DD, hn[code]), code);
            }
            id = keyCode(warpMaxU64(myKey));
        }
    } else {
        unsigned long long bk = 0ULL;
        for (int c = lane; c < CC; c += 32) {
            unsigned long long k = makeKey(exact_score(rrow, cb + (size_t)c * DD, hn[c]), c);
            if (k > bk) bk = k;
        }
        id = keyCode(warpMaxU64(bk));
    }
    if (lane == 0) {
        g_candcnt[row] = 0;                        // reset for next stage
        if (outIdxF) outIdxF[(size_t)row * QQ + stage] = (float)id;
    }
    float lsum = do_update(row, id, lane, cb, r0, r1, r2, r3, writeA, x, outQ);
    if (lane == 0) g_partial[(size_t)stage * MTOT + row] = lsum;

    cudaTriggerProgrammaticLaunchCompletion();     // all writes done; let next gemm start
}

// ---------------- losses: 8-way parallel per-stage reduction (same order) ------
__global__ void losses_partial() {
    __shared__ float red[256];
    int q = blockIdx.x, tid = threadIdx.x;
    float s = 0.f;
    for (int i = tid; i < MTOT; i += 256) s += g_partial[(size_t)q * MTOT + i];
    red[tid] = s;
    __syncthreads();
    for (int st = 128; st > 0; st >>= 1) {
        if (tid < st) red[tid] += red[tid + st];
        __syncthreads();
    }
    if (tid == 0) g_stageLoss[q] = red[0] * (COMMIT_W / ((float)MTOT * (float)DD));
}
__global__ void losses_final(float* outLoss, float* outFinal) {
    if (threadIdx.x == 0) {
        float tot = 0.f;
        for (int q = 0; q < QQ; ++q) {
            float v = g_stageLoss[q];
            if (outLoss) outLoss[q] = v;
            tot += v;
        }
        if (outFinal) *outFinal = tot;
    }
}

__global__ void finalize_kernel(const float* __restrict__ x, float* __restrict__ out, size_t n) {
    size_t i = (size_t)blockIdx.x * blockDim.x + threadIdx.x;
    if (i < n) out[i] = x[i] - g_resid[i];
}
__global__ void zero_tail(float* out, size_t start, size_t end) {
    size_t i = start + (size_t)blockIdx.x * blockDim.x + threadIdx.x;
    if (i < end) out[i] = 0.f;
}

// ---------------- PDL launch helpers (fallback to plain launch) ----------------
static inline void launch_gemm_pdl(int stage) {
    cudaLaunchConfig_t cfg = {};
    cfg.gridDim = dim3(4096); cfg.blockDim = dim3(256);
    cfg.dynamicSmemBytes = 65536; cfg.stream = 0;
    cudaLaunchAttribute attr[1];
    attr[0].id = cudaLaunchAttributeProgrammaticStreamSerialization;
    attr[0].val.programmaticStreamSerializationAllowed = 1;
    cfg.attrs = attr; cfg.numAttrs = 1;
    if (cudaLaunchKernelEx(&cfg, gemm_score, stage) != cudaSuccess)
        gemm_score<<<4096, 256, 65536>>>(stage);
}
static inline void launch_resolve_pdl(const float* cb, int stage, float* outIdxF,
                                      int writeA, const float* x, float* outQ) {
    cudaLaunchConfig_t cfg = {};
    cfg.gridDim = dim3(MTOT / 8); cfg.blockDim = dim3(256);
    cfg.dynamicSmemBytes = 0; cfg.stream = 0;
    cudaLaunchAttribute attr[1];
    attr[0].id = cudaLaunchAttributeProgrammaticStreamSerialization;
    attr[0].val.programmaticStreamSerializationAllowed = 1;
    cfg.attrs = attr; cfg.numAttrs = 1;
    if (cudaLaunchKernelEx(&cfg, resolve_update, cb, stage, outIdxF, writeA, x, outQ)
        != cudaSuccess)
        resolve_update<<<MTOT / 8, 256>>>(cb, stage, outIdxF, writeA, x, outQ);
}

// ---------------- launch ----------------
extern "C" void kernel_launch(void* const* d_in, const int* in_sizes, int n_in,
                              void* d_out, int out_size) {
    const float* x  = (const float*)d_in[0];
    const float* cb = (const float*)d_in[1];
    if (n_in >= 2 && in_sizes[0] == QQ * CC * DD && in_sizes[1] == (int)MD) {
        x = (const float*)d_in[1]; cb = (const float*)d_in[0];
    }
    cudaFuncSetAttribute(gemm_score, cudaFuncAttributeMaxDynamicSharedMemorySize, 65536);

    float* out = (float*)d_out;
    const size_t offI = MD, offL = offI + (size_t)MTOT * QQ, offF = offL + QQ, tot = offF + 1;
    size_t osz = (size_t)out_size;
    float* outIdxF  = (osz >= offL) ? out + offI : nullptr;
    float* outLoss  = (osz >= offF) ? out + offL : nullptr;
    float* outFinal = (osz >= tot)  ? out + offF : nullptr;
    bool fuseFinal = (osz >= MD);

    init_kernel<<<MTOT / 4, 256>>>(x);
    convert_B<<<QQ * CC / 4, 256>>>(cb);
    halfnorm_kernel<<<QQ * CC, 128>>>(cb);

    for (int q = 0; q < QQ; ++q) {
        launch_gemm_pdl(q);
        bool last = (q == QQ - 1);
        float* oq = (last && fuseFinal) ? out : nullptr;
        launch_resolve_pdl(cb, q, outIdxF, last ? 0 : 1, x, oq);
    }
    losses_partial<<<QQ, 256>>>();
    losses_final<<<1, 32>>>(outLoss, outFinal);

    if (!fuseFinal && osz > 0)
        finalize_kernel<<<(unsigned)((osz + 255) / 256), 256>>>(x, out, osz);
    if (osz > tot)
        zero_tail<<<(unsigned)((osz - tot + 255) / 256), 256>>>(out, tot, osz);
}